// round 15
// baseline (speedup 1.0000x reference)
#include <cuda_runtime.h>

#define T_STEPS 2048
#define B_SIZE  4096
#define OUTD    4
#define NCHUNK  2
#define WARMUP  64
#define T_SPLIT 1056        // chunk0: [0,1056) no warmup; chunk1: warm [992,1056), out [1056,2048)
#define BLOCK_THREADS 32

typedef unsigned long long u64;

// partial sums: [chunk][b*8+sub]
__device__ float g_part[NCHUNK * B_SIZE * 8];

// ---------- packed f32x2 helpers (sm_100a) ----------
__device__ __forceinline__ u64 pack2(float lo, float hi) {
    u64 r;
    asm("mov.b64 %0, {%1, %2};"
        : "=l"(r) : "r"(__float_as_uint(lo)), "r"(__float_as_uint(hi)));
    return r;
}
__device__ __forceinline__ void unpack2(u64 v, float& lo, float& hi) {
    unsigned a, b;
    asm("mov.b64 {%0, %1}, %2;" : "=r"(a), "=r"(b) : "l"(v));
    lo = __uint_as_float(a);
    hi = __uint_as_float(b);
}
__device__ __forceinline__ u64 fma2(u64 a, u64 b, u64 c) {
    u64 d;
    asm("fma.rn.f32x2 %0, %1, %2, %3;" : "=l"(d) : "l"(a), "l"(b), "l"(c));
    return d;
}
__device__ __forceinline__ u64 add2(u64 a, u64 b) {
    u64 d;
    asm("add.rn.f32x2 %0, %1, %2;" : "=l"(d) : "l"(a), "l"(b));
    return d;
}
__device__ __forceinline__ float tanh_mufu(float x) {
    float r; asm("tanh.approx.f32 %0, %1;" : "=f"(r) : "f"(x)); return r;
}

// tree dot (critical path): 2 parallel chains + combine
__device__ __forceinline__ float dott(const u64 (&w)[4], const u64 (&p)[4]) {
    u64 a = fma2(w[0], p[0], 0ULL);
    u64 b = fma2(w[1], p[1], 0ULL);
    a = fma2(w[2], p[2], a);
    b = fma2(w[3], p[3], b);
    u64 s = add2(a, b);
    float lo, hi;
    unpack2(s, lo, hi);
    return lo + hi;
}
// serial dot (off critical path): 4-chain, fewest instructions
__device__ __forceinline__ float dots(const u64 (&w)[4], const u64 (&p)[4], float bias) {
    u64 a = fma2(w[0], p[0], 0ULL);
    a = fma2(w[1], p[1], a);
    a = fma2(w[2], p[2], a);
    a = fma2(w[3], p[3], a);
    float lo, hi;
    unpack2(a, lo, hi);
    return (lo + bias) + hi;
}

// 1 warp per block, 4 batch elements per warp (8 lanes each), all 3 layers
// in-thread, h broadcast via 3 distinct smem buffers (1 syncwarp per layer),
// time split into 2 equal-work chunks (chunk1 re-warms 64 steps).
__global__ void __launch_bounds__(BLOCK_THREADS)
gru3_fused_kernel(const float* __restrict__ x,
                  const float* __restrict__ Wih0, const float* __restrict__ Whh0,
                  const float* __restrict__ bih0, const float* __restrict__ bhh0,
                  const float* __restrict__ Wih1, const float* __restrict__ Whh1,
                  const float* __restrict__ bih1, const float* __restrict__ bhh1,
                  const float* __restrict__ Wih2, const float* __restrict__ Whh2,
                  const float* __restrict__ bih2, const float* __restrict__ bhh2)
{
    const int lane  = threadIdx.x;
    const int e     = lane >> 3;
    const int sub   = lane & 7;
    const int chunk = blockIdx.x & 1;
    const int b     = (blockIdx.x >> 1) * 4 + e;

    __shared__ __align__(8) float s_h0[32];
    __shared__ __align__(8) float s_h1[32];
    __shared__ __align__(8) float s_h2[32];

    // ---- packed register-resident weights (0.5-folded for r/z; tanh-form sigmoid)
    u64 whh0[3][4], whh1[3][4], whh2[3][4];
    u64 wih1[3][4], wih2[3][4];
    float wxa[3], wxb[3];

    const float2* Whh0v = (const float2*)Whh0;
    const float2* Whh1v = (const float2*)Whh1;
    const float2* Whh2v = (const float2*)Whh2;
    const float2* Wih1v = (const float2*)Wih1;
    const float2* Wih2v = (const float2*)Wih2;

#pragma unroll
    for (int gt = 0; gt < 3; gt++) {
        const int row = gt * 8 + sub;
        const float sih = (gt < 2) ? 0.5f : 1.0f;
#pragma unroll
        for (int kk = 0; kk < 4; kk++) {
            float2 a = Whh0v[row * 4 + kk]; whh0[gt][kk] = pack2(0.5f * a.x, 0.5f * a.y);
            float2 c = Whh1v[row * 4 + kk]; whh1[gt][kk] = pack2(0.5f * c.x, 0.5f * c.y);
            float2 g = Whh2v[row * 4 + kk]; whh2[gt][kk] = pack2(0.5f * g.x, 0.5f * g.y);
            float2 d = Wih1v[row * 4 + kk]; wih1[gt][kk] = pack2(sih * d.x, sih * d.y);
            float2 f = Wih2v[row * 4 + kk]; wih2[gt][kk] = pack2(sih * f.x, sih * f.y);
        }
        wxa[gt] = sih * Wih0[row * 2 + 0];
        wxb[gt] = sih * Wih0[row * 2 + 1];
    }

    const float bR0 = 0.5f * (bih0[sub] + bhh0[sub]);
    const float bZ0 = 0.5f * (bih0[8 + sub] + bhh0[8 + sub]);
    const float bX0 = bih0[16 + sub];
    const float bH0 = 0.5f * bhh0[16 + sub];
    const float bR1 = 0.5f * (bih1[sub] + bhh1[sub]);
    const float bZ1 = 0.5f * (bih1[8 + sub] + bhh1[8 + sub]);
    const float bX1 = bih1[16 + sub];
    const float bH1 = 0.5f * bhh1[16 + sub];
    const float bR2 = 0.5f * (bih2[sub] + bhh2[sub]);
    const float bZ2 = 0.5f * (bih2[8 + sub] + bhh2[8 + sub]);
    const float bX2 = bih2[16 + sub];
    const float bH2 = 0.5f * bhh2[16 + sub];

    // state: h + eager hh partials (bias included)
    float h0 = 0.0f, h1 = 0.0f, h2 = 0.0f, acc = 0.0f;
    float rc0 = bR0, zc0 = bZ0, uc0 = bH0;
    float rc1 = bR1, zc1 = bZ1, uc1 = bH1;
    float rc2 = bR2, zc2 = bZ2, uc2 = bH2;

    const int t_out   = chunk ? T_SPLIT : 0;
    const int t_end   = chunk ? T_STEPS : T_SPLIT;
    const int t_start = chunk ? (T_SPLIT - WARMUP) : 0;

    const float* xb = x + (size_t)b * 2;
    float2 cx = __ldg((const float2*)(xb + (size_t)t_start * (B_SIZE * 2)));

    auto step = [&](float2 xc) {
        // ================= layer 0 =================
        float aR0 = fmaf(wxa[0], xc.x, fmaf(wxb[0], xc.y, rc0));
        float aZ0 = fmaf(wxa[1], xc.x, fmaf(wxb[1], xc.y, zc0));
        float c0  = fmaf(wxa[2], xc.x, fmaf(wxb[2], xc.y, uc0 + bX0));
        float sr0 = tanh_mufu(aR0);
        float sz0 = tanh_mufu(aZ0);
        float n0  = tanh_mufu(fmaf(sr0, uc0, c0));
        float A0  = 0.5f * h0;
        h0 = fmaf(sz0, fmaf(-0.5f, n0, A0), fmaf(0.5f, n0, A0));

        s_h0[lane] = h0;
        __syncwarp();                 // WAR on s_h2 (prev iter) also covered here
        u64 P0[4];
        {
            const u64* q = (const u64*)&s_h0[e * 8];
            P0[0] = q[0]; P0[1] = q[1]; P0[2] = q[2]; P0[3] = q[3];
        }
        rc0 = dots(whh0[0], P0, bR0);
        zc0 = dots(whh0[1], P0, bZ0);
        uc0 = dots(whh0[2], P0, bH0);

        // ================= layer 1 (vin = h0 via P0) =================
        float aR1 = dott(wih1[0], P0) + rc1;
        float aZ1 = dott(wih1[1], P0) + zc1;
        float c1  = dott(wih1[2], P0) + (uc1 + bX1);
        float sr1 = tanh_mufu(aR1);
        float sz1 = tanh_mufu(aZ1);
        float n1  = tanh_mufu(fmaf(sr1, uc1, c1));
        float A1  = 0.5f * h1;
        h1 = fmaf(sz1, fmaf(-0.5f, n1, A1), fmaf(0.5f, n1, A1));

        s_h1[lane] = h1;
        __syncwarp();                 // orders: reads of s_h0 done before next write
        u64 P1[4];
        {
            const u64* q = (const u64*)&s_h1[e * 8];
            P1[0] = q[0]; P1[1] = q[1]; P1[2] = q[2]; P1[3] = q[3];
        }
        rc1 = dots(whh1[0], P1, bR1);
        zc1 = dots(whh1[1], P1, bZ1);
        uc1 = dots(whh1[2], P1, bH1);

        // ================= layer 2 (vin = h1 via P1) =================
        float aR2 = dott(wih2[0], P1) + rc2;
        float aZ2 = dott(wih2[1], P1) + zc2;
        float c2  = dott(wih2[2], P1) + (uc2 + bX2);
        float sr2 = tanh_mufu(aR2);
        float sz2 = tanh_mufu(aZ2);
        float n2  = tanh_mufu(fmaf(sr2, uc2, c2));
        float A2  = 0.5f * h2;
        h2 = fmaf(sz2, fmaf(-0.5f, n2, A2), fmaf(0.5f, n2, A2));

        s_h2[lane] = h2;
        __syncwarp();
        u64 P2[4];
        {
            const u64* q = (const u64*)&s_h2[e * 8];
            P2[0] = q[0]; P2[1] = q[1]; P2[2] = q[2]; P2[3] = q[3];
        }
        rc2 = dots(whh2[0], P2, bR2);
        zc2 = dots(whh2[1], P2, bZ2);
        uc2 = dots(whh2[2], P2, bH2);
    };

    // ---- warm-up (chunk 1 only; no accumulation) ----
#pragma unroll 1
    for (int t = t_start; t < t_out; t++) {
        float2 nx = __ldg((const float2*)(xb + (size_t)(t + 1) * (B_SIZE * 2)));
        step(cx);
        cx = nx;
    }
    // ---- output loop ----
#pragma unroll 1
    for (int t = t_out; t < t_end; t++) {
        const int tn = (t + 1 < T_STEPS) ? (t + 1) : (T_STEPS - 1);
        float2 nx = __ldg((const float2*)(xb + (size_t)tn * (B_SIZE * 2)));
        step(cx);
        acc += h2;
        cx = nx;
    }

    g_part[chunk * (B_SIZE * 8) + b * 8 + sub] = acc;
}

__global__ void __launch_bounds__(256)
gru3_finalize_kernel(const float* __restrict__ fcW, const float* __restrict__ fcb,
                     float* __restrict__ out)
{
    const int i   = blockIdx.x * 256 + threadIdx.x;  // b*8+sub
    const int b   = i >> 3;
    const int sub = i & 7;

    float s = g_part[i] + g_part[B_SIZE * 8 + i];
    const float mean = s * (1.0f / (float)T_STEPS);

    float m[8];
#pragma unroll
    for (int k = 0; k < 8; k++)
        m[k] = __shfl_sync(0xffffffffu, mean, k, 8);

    if (sub < OUTD) {
        float o = __ldg(fcb + sub);
#pragma unroll
        for (int k = 0; k < 8; k++)
            o = fmaf(__ldg(fcW + sub * 8 + k), m[k], o);
        out[(size_t)b * OUTD + sub] = o;
    }
}

extern "C" void kernel_launch(void* const* d_in, const int* in_sizes, int n_in,
                              void* d_out, int out_size)
{
    const float* x    = (const float*)d_in[0];
    const float* Wih0 = (const float*)d_in[1];
    const float* Whh0 = (const float*)d_in[2];
    const float* bih0 = (const float*)d_in[3];
    const float* bhh0 = (const float*)d_in[4];
    const float* Wih1 = (const float*)d_in[5];
    const float* Whh1 = (const float*)d_in[6];
    const float* bih1 = (const float*)d_in[7];
    const float* bhh1 = (const float*)d_in[8];
    const float* Wih2 = (const float*)d_in[9];
    const float* Whh2 = (const float*)d_in[10];
    const float* bih2 = (const float*)d_in[11];
    const float* bhh2 = (const float*)d_in[12];
    const float* fcW  = (const float*)d_in[13];
    const float* fcb  = (const float*)d_in[14];
    float* out = (float*)d_out;

    // 4 elements per warp-block, 2 time chunks -> 2048 blocks of 32 threads
    gru3_fused_kernel<<<(B_SIZE / 4) * NCHUNK, BLOCK_THREADS>>>(
        x,
        Wih0, Whh0, bih0, bhh0,
        Wih1, Whh1, bih1, bhh1,
        Wih2, Whh2, bih2, bhh2);

    gru3_finalize_kernel<<<(B_SIZE * 8) / 256, 256>>>(fcW, fcb, out);
}

// round 16
// speedup vs baseline: 1.0689x; 1.0689x over previous
#include <cuda_runtime.h>

#define T_STEPS 2048
#define B_SIZE  4096
#define OUTD    4
#define WARMUP  64
#define ITERS   1056          // per-chain steps; chunk0=[0,1056), chunk1 warm[992,1056)+out[1056,2048)
#define OFF1    992           // chunk1 start
#define BLOCK_THREADS 32

typedef unsigned long long u64;

// ---------- packed f32x2 helpers (sm_100a) ----------
__device__ __forceinline__ u64 pack2(float lo, float hi) {
    u64 r;
    asm("mov.b64 %0, {%1, %2};"
        : "=l"(r) : "r"(__float_as_uint(lo)), "r"(__float_as_uint(hi)));
    return r;
}
__device__ __forceinline__ void unpack2(u64 v, float& lo, float& hi) {
    unsigned a, b;
    asm("mov.b64 {%0, %1}, %2;" : "=r"(a), "=r"(b) : "l"(v));
    lo = __uint_as_float(a);
    hi = __uint_as_float(b);
}
__device__ __forceinline__ u64 fma2(u64 a, u64 b, u64 c) {
    u64 d;
    asm("fma.rn.f32x2 %0, %1, %2, %3;" : "=l"(d) : "l"(a), "l"(b), "l"(c));
    return d;
}
__device__ __forceinline__ u64 add2(u64 a, u64 b) {
    u64 d;
    asm("add.rn.f32x2 %0, %1, %2;" : "=l"(d) : "l"(a), "l"(b));
    return d;
}
__device__ __forceinline__ float tanh_mufu(float x) {
    float r; asm("tanh.approx.f32 %0, %1;" : "=f"(r) : "f"(x)); return r;
}

// tree dot (critical path): 2 parallel chains + combine
__device__ __forceinline__ float dott(const u64 (&w)[4], const u64 (&p)[4]) {
    u64 a = fma2(w[0], p[0], 0ULL);
    u64 b = fma2(w[1], p[1], 0ULL);
    a = fma2(w[2], p[2], a);
    b = fma2(w[3], p[3], b);
    u64 s = add2(a, b);
    float lo, hi;
    unpack2(s, lo, hi);
    return lo + hi;
}
// serial dot (off critical path): fewest instructions
__device__ __forceinline__ float dots(const u64 (&w)[4], const u64 (&p)[4], float bias) {
    u64 a = fma2(w[0], p[0], 0ULL);
    a = fma2(w[1], p[1], a);
    a = fma2(w[2], p[2], a);
    a = fma2(w[3], p[3], a);
    float lo, hi;
    unpack2(a, lo, hi);
    return (lo + bias) + hi;
}

// 1 warp per block, 4 batch elements (8 lanes each). Each thread advances TWO
// independent time-chunks of the same element (time-ILP): same weights, two
// recurrence chains interleaved. Broadcast via smem; one syncwarp per layer
// covers both chains.
__global__ void __launch_bounds__(BLOCK_THREADS)
gru3_fused_kernel(const float* __restrict__ x,
                  const float* __restrict__ Wih0, const float* __restrict__ Whh0,
                  const float* __restrict__ bih0, const float* __restrict__ bhh0,
                  const float* __restrict__ Wih1, const float* __restrict__ Whh1,
                  const float* __restrict__ bih1, const float* __restrict__ bhh1,
                  const float* __restrict__ Wih2, const float* __restrict__ Whh2,
                  const float* __restrict__ bih2, const float* __restrict__ bhh2,
                  const float* __restrict__ fcW,  const float* __restrict__ fcb,
                  float* __restrict__ out)
{
    const int lane = threadIdx.x;
    const int e    = lane >> 3;
    const int sub  = lane & 7;
    const int b    = blockIdx.x * 4 + e;

    // per-layer, per-chain broadcast buffers
    __shared__ __align__(8) float s_h0[2][32];
    __shared__ __align__(8) float s_h1[2][32];
    __shared__ __align__(8) float s_h2[2][32];

    // ---- packed register-resident weights (0.5-folded r/z; tanh-form sigmoid)
    u64 whh0[3][4], whh1[3][4], whh2[3][4];
    u64 wih1[3][4], wih2[3][4];
    float wxa[3], wxb[3];

    const float2* Whh0v = (const float2*)Whh0;
    const float2* Whh1v = (const float2*)Whh1;
    const float2* Whh2v = (const float2*)Whh2;
    const float2* Wih1v = (const float2*)Wih1;
    const float2* Wih2v = (const float2*)Wih2;

#pragma unroll
    for (int gt = 0; gt < 3; gt++) {
        const int row = gt * 8 + sub;
        const float sih = (gt < 2) ? 0.5f : 1.0f;
#pragma unroll
        for (int kk = 0; kk < 4; kk++) {
            float2 a = Whh0v[row * 4 + kk]; whh0[gt][kk] = pack2(0.5f * a.x, 0.5f * a.y);
            float2 c = Whh1v[row * 4 + kk]; whh1[gt][kk] = pack2(0.5f * c.x, 0.5f * c.y);
            float2 g = Whh2v[row * 4 + kk]; whh2[gt][kk] = pack2(0.5f * g.x, 0.5f * g.y);
            float2 d = Wih1v[row * 4 + kk]; wih1[gt][kk] = pack2(sih * d.x, sih * d.y);
            float2 f = Wih2v[row * 4 + kk]; wih2[gt][kk] = pack2(sih * f.x, sih * f.y);
        }
        wxa[gt] = sih * Wih0[row * 2 + 0];
        wxb[gt] = sih * Wih0[row * 2 + 1];
    }

    const float bR0 = 0.5f * (bih0[sub] + bhh0[sub]);
    const float bZ0 = 0.5f * (bih0[8 + sub] + bhh0[8 + sub]);
    const float bX0 = bih0[16 + sub];
    const float bH0 = 0.5f * bhh0[16 + sub];
    const float bR1 = 0.5f * (bih1[sub] + bhh1[sub]);
    const float bZ1 = 0.5f * (bih1[8 + sub] + bhh1[8 + sub]);
    const float bX1 = bih1[16 + sub];
    const float bH1 = 0.5f * bhh1[16 + sub];
    const float bR2 = 0.5f * (bih2[sub] + bhh2[sub]);
    const float bZ2 = 0.5f * (bih2[8 + sub] + bhh2[8 + sub]);
    const float bX2 = bih2[16 + sub];
    const float bH2 = 0.5f * bhh2[16 + sub];

    // dual-chain state: h + eager hh partials (bias included)
    float h0[2] = {0.0f, 0.0f}, h1[2] = {0.0f, 0.0f}, h2[2] = {0.0f, 0.0f};
    float rc0[2] = {bR0, bR0}, zc0[2] = {bZ0, bZ0}, uc0[2] = {bH0, bH0};
    float rc1[2] = {bR1, bR1}, zc1[2] = {bZ1, bZ1}, uc1[2] = {bH1, bH1};
    float rc2[2] = {bR2, bR2}, zc2[2] = {bZ2, bZ2}, uc2[2] = {bH2, bH2};
    float acc0 = 0.0f, acc1 = 0.0f;

    const float* xb = x + (size_t)b * 2;
    float2 cx[2];
    cx[0] = __ldg((const float2*)xb);
    cx[1] = __ldg((const float2*)(xb + (size_t)OFF1 * (B_SIZE * 2)));

#pragma unroll 1
    for (int i = 0; i < ITERS; i++) {
        // prefetch both chains' next x (chunk0: i+1 <= 1056 < 2048 always valid)
        float2 nx0 = __ldg((const float2*)(xb + (size_t)(i + 1) * (B_SIZE * 2)));
        const int t1n = (OFF1 + i + 1 < T_STEPS) ? (OFF1 + i + 1) : (T_STEPS - 1);
        float2 nx1 = __ldg((const float2*)(xb + (size_t)t1n * (B_SIZE * 2)));

        // ================= layer 0 (both chains) =================
#pragma unroll
        for (int c = 0; c < 2; c++) {
            float aR = fmaf(wxa[0], cx[c].x, fmaf(wxb[0], cx[c].y, rc0[c]));
            float aZ = fmaf(wxa[1], cx[c].x, fmaf(wxb[1], cx[c].y, zc0[c]));
            float cc = fmaf(wxa[2], cx[c].x, fmaf(wxb[2], cx[c].y, uc0[c] + bX0));
            float sr = tanh_mufu(aR);
            float sz = tanh_mufu(aZ);
            float n  = tanh_mufu(fmaf(sr, uc0[c], cc));
            float A  = 0.5f * h0[c];
            h0[c] = fmaf(sz, fmaf(-0.5f, n, A), fmaf(0.5f, n, A));
            s_h0[c][lane] = h0[c];
        }
        __syncwarp();
        u64 P0[2][4];
#pragma unroll
        for (int c = 0; c < 2; c++) {
            const u64* q = (const u64*)&s_h0[c][e * 8];
            P0[c][0] = q[0]; P0[c][1] = q[1]; P0[c][2] = q[2]; P0[c][3] = q[3];
            rc0[c] = dots(whh0[0], P0[c], bR0);
            zc0[c] = dots(whh0[1], P0[c], bZ0);
            uc0[c] = dots(whh0[2], P0[c], bH0);
        }

        // ================= layer 1 (both chains) =================
#pragma unroll
        for (int c = 0; c < 2; c++) {
            float aR = dott(wih1[0], P0[c]) + rc1[c];
            float aZ = dott(wih1[1], P0[c]) + zc1[c];
            float cc = dott(wih1[2], P0[c]) + (uc1[c] + bX1);
            float sr = tanh_mufu(aR);
            float sz = tanh_mufu(aZ);
            float n  = tanh_mufu(fmaf(sr, uc1[c], cc));
            float A  = 0.5f * h1[c];
            h1[c] = fmaf(sz, fmaf(-0.5f, n, A), fmaf(0.5f, n, A));
            s_h1[c][lane] = h1[c];
        }
        __syncwarp();
        u64 P1[2][4];
#pragma unroll
        for (int c = 0; c < 2; c++) {
            const u64* q = (const u64*)&s_h1[c][e * 8];
            P1[c][0] = q[0]; P1[c][1] = q[1]; P1[c][2] = q[2]; P1[c][3] = q[3];
            rc1[c] = dots(whh1[0], P1[c], bR1);
            zc1[c] = dots(whh1[1], P1[c], bZ1);
            uc1[c] = dots(whh1[2], P1[c], bH1);
        }

        // ================= layer 2 (both chains) =================
#pragma unroll
        for (int c = 0; c < 2; c++) {
            float aR = dott(wih2[0], P1[c]) + rc2[c];
            float aZ = dott(wih2[1], P1[c]) + zc2[c];
            float cc = dott(wih2[2], P1[c]) + (uc2[c] + bX2);
            float sr = tanh_mufu(aR);
            float sz = tanh_mufu(aZ);
            float n  = tanh_mufu(fmaf(sr, uc2[c], cc));
            float A  = 0.5f * h2[c];
            h2[c] = fmaf(sz, fmaf(-0.5f, n, A), fmaf(0.5f, n, A));
            s_h2[c][lane] = h2[c];
        }
        __syncwarp();
        u64 P2[2][4];
#pragma unroll
        for (int c = 0; c < 2; c++) {
            const u64* q = (const u64*)&s_h2[c][e * 8];
            P2[c][0] = q[0]; P2[c][1] = q[1]; P2[c][2] = q[2]; P2[c][3] = q[3];
            rc2[c] = dots(whh2[0], P2[c], bR2);
            zc2[c] = dots(whh2[1], P2[c], bZ2);
            uc2[c] = dots(whh2[2], P2[c], bH2);
        }

        acc0 += h2[0];
        if (i >= WARMUP) acc1 += h2[1];

        cx[0] = nx0;
        cx[1] = nx1;
    }

    // ---- mean over T (both chunks local), then FC (OUT=4) ----
    __syncwarp();
    s_h0[0][lane] = (acc0 + acc1) * (1.0f / (float)T_STEPS);
    __syncwarp();
    if (sub < OUTD) {
        float o = __ldg(fcb + sub);
#pragma unroll
        for (int k = 0; k < 8; k++)
            o = fmaf(__ldg(fcW + sub * 8 + k), s_h0[0][e * 8 + k], o);
        out[(size_t)b * OUTD + sub] = o;
    }
}

extern "C" void kernel_launch(void* const* d_in, const int* in_sizes, int n_in,
                              void* d_out, int out_size)
{
    const float* x    = (const float*)d_in[0];
    const float* Wih0 = (const float*)d_in[1];
    const float* Whh0 = (const float*)d_in[2];
    const float* bih0 = (const float*)d_in[3];
    const float* bhh0 = (const float*)d_in[4];
    const float* Wih1 = (const float*)d_in[5];
    const float* Whh1 = (const float*)d_in[6];
    const float* bih1 = (const float*)d_in[7];
    const float* bhh1 = (const float*)d_in[8];
    const float* Wih2 = (const float*)d_in[9];
    const float* Whh2 = (const float*)d_in[10];
    const float* bih2 = (const float*)d_in[11];
    const float* bhh2 = (const float*)d_in[12];
    const float* fcW  = (const float*)d_in[13];
    const float* fcb  = (const float*)d_in[14];
    float* out = (float*)d_out;

    // 4 elements per warp-block -> 1024 blocks, single wave (~7/SM)
    gru3_fused_kernel<<<B_SIZE / 4, BLOCK_THREADS>>>(
        x,
        Wih0, Whh0, bih0, bhh0,
        Wih1, Whh1, bih1, bhh1,
        Wih2, Whh2, bih2, bhh2,
        fcW, fcb, out);
}